// round 1
// baseline (speedup 1.0000x reference)
#include <cuda_runtime.h>
#include <cuda_bf16.h>
#include <math.h>

// Problem constants (fixed by the dataset)
#define E_  16
#define K_  4
#define H_  1024
#define F_  2048
#define T_  4096            // SL*BS
#define N_  (T_ * K_)       // 16384 routed copies
#define C_  1024            // capacity per expert = K*T/E
#define ALPHA_ 1.702f
#define LIMIT_ 7.0f

#define BM 128
#define BN 128
#define BK 16

// -------------------- scratch (device globals; no runtime allocs) ----------
__device__ float g_act[(size_t)E_ * C_ * F_];   // 128 MB activation scratch
__device__ int   g_slot_tok[E_ * C_];           // slot -> source token
__device__ float g_slot_w[E_ * C_];             // slot -> combine weight
__device__ int   g_cnt[E_];                     // min(tokens_per_expert, C)
__device__ int   g_te[N_];                      // expert id per copy
__device__ float g_ew[N_];                      // softmax weight per copy

// -------------------- zero output -----------------------------------------
__global__ void zero_kernel(float* __restrict__ p, size_t n) {
    size_t i = (size_t)blockIdx.x * blockDim.x + threadIdx.x;
    size_t stride = (size_t)gridDim.x * blockDim.x;
    for (; i < n; i += stride) p[i] = 0.0f;
}

// -------------------- router: logits, top-4, softmax, scores --------------
__global__ void router_kernel(const float* __restrict__ xf,
                              const float* __restrict__ rw,
                              const float* __restrict__ rb,
                              float* __restrict__ ew_out,   // [T,K] or null
                              float* __restrict__ rs_out) { // [E,T] or null
    int t = blockIdx.x;
    int lane = threadIdx.x & 31;
    int w = threadIdx.x >> 5;          // warp 0..3, handles experts 4w..4w+3
    __shared__ float logits[E_];

    const float* xr = xf + (size_t)t * H_;
    float s0 = 0.f, s1 = 0.f, s2 = 0.f, s3 = 0.f;
    const float* r0 = rw + (size_t)(4 * w + 0) * H_;
    const float* r1 = rw + (size_t)(4 * w + 1) * H_;
    const float* r2 = rw + (size_t)(4 * w + 2) * H_;
    const float* r3 = rw + (size_t)(4 * w + 3) * H_;
    for (int i = lane; i < H_; i += 32) {
        float xv = xr[i];
        s0 += xv * r0[i];
        s1 += xv * r1[i];
        s2 += xv * r2[i];
        s3 += xv * r3[i];
    }
    #pragma unroll
    for (int o = 16; o > 0; o >>= 1) {
        s0 += __shfl_xor_sync(0xffffffff, s0, o);
        s1 += __shfl_xor_sync(0xffffffff, s1, o);
        s2 += __shfl_xor_sync(0xffffffff, s2, o);
        s3 += __shfl_xor_sync(0xffffffff, s3, o);
    }
    if (lane == 0) {
        logits[4 * w + 0] = s0 + rb[4 * w + 0];
        logits[4 * w + 1] = s1 + rb[4 * w + 1];
        logits[4 * w + 2] = s2 + rb[4 * w + 2];
        logits[4 * w + 3] = s3 + rb[4 * w + 3];
    }
    __syncthreads();

    if (threadIdx.x == 0) {
        float lv[E_];
        #pragma unroll
        for (int e = 0; e < E_; e++) lv[e] = logits[e];
        int   idx[K_];
        float val[K_];
        bool  used[E_];
        #pragma unroll
        for (int e = 0; e < E_; e++) used[e] = false;
        // top-k: strictly-greater compare with ascending scan -> lowest index
        // wins ties (matches jax.lax.top_k stable semantics)
        for (int k = 0; k < K_; k++) {
            float best = -INFINITY; int bi = 0;
            for (int e = 0; e < E_; e++)
                if (!used[e] && lv[e] > best) { best = lv[e]; bi = e; }
            used[bi] = true; idx[k] = bi; val[k] = best;
        }
        // softmax over the k selected (val[0] is the max)
        float m = val[0], sum = 0.f, p[K_];
        for (int k = 0; k < K_; k++) { p[k] = expf(val[k] - m); sum += p[k]; }
        float inv = 1.0f / sum;
        float sc[E_];
        #pragma unroll
        for (int e = 0; e < E_; e++) sc[e] = 0.f;
        for (int k = 0; k < K_; k++) {
            float wk = p[k] * inv;
            g_ew[t * K_ + k] = wk;
            g_te[t * K_ + k] = idx[k];
            if (ew_out) ew_out[t * K_ + k] = wk;
            sc[idx[k]] = wk;
        }
        if (rs_out) {
            for (int e = 0; e < E_; e++) rs_out[(size_t)e * T_ + t] = sc[e];
        }
    }
}

// -------------------- binning: stable counting sort by expert --------------
// single CTA of 512 threads, each owns 32 consecutive copies
__global__ void binning_kernel() {
    __shared__ int cnts[512 * E_];
    __shared__ int tot[E_];
    int tid = threadIdx.x;
    int base = tid * 32;

    int loc[E_];
    #pragma unroll
    for (int e = 0; e < E_; e++) loc[e] = 0;
    for (int i = 0; i < 32; i++) loc[g_te[base + i]]++;
    #pragma unroll
    for (int e = 0; e < E_; e++) cnts[tid * E_ + e] = loc[e];
    __syncthreads();

    // per-expert exclusive prefix across the 512 threads (16 scanners)
    if (tid < E_) {
        int run = 0;
        for (int i = 0; i < 512; i++) {
            int c = cnts[i * E_ + tid];
            cnts[i * E_ + tid] = run;
            run += c;
        }
        tot[tid] = run;
        g_cnt[tid] = run < C_ ? run : C_;
    }
    __syncthreads();

    // assign slots (per-expert rank), drop rank >= capacity
    #pragma unroll
    for (int e = 0; e < E_; e++) loc[e] = cnts[tid * E_ + e];
    for (int i = 0; i < 32; i++) {
        int n = base + i;
        int e = g_te[n];
        int rank = loc[e]++;
        if (rank < C_) {
            int slot = e * C_ + rank;
            g_slot_tok[slot] = n >> 2;     // / K_
            g_slot_w[slot]   = g_ew[n];
        }
    }
}

// -------------------- GEMM1: xb @ w1 + b1 -> interleaved GLU -> g_act ------
__global__ void __launch_bounds__(256, 2)
gemm1_kernel(const float* __restrict__ xf,
             const float* __restrict__ w1,
             const float* __restrict__ w1_bias) {
    int e = blockIdx.z;
    int cnt = g_cnt[e];
    int m0 = blockIdx.y * BM;
    if (m0 >= cnt) return;
    int n0 = blockIdx.x * BN;

    const float* B = w1 + (size_t)e * H_ * (2 * F_);

    __shared__ float As[BK][BM + 4];
    __shared__ float Bs[BK][BN];

    int tid = threadIdx.x;
    int tx = tid & 15;
    int ty = tid >> 4;

    float acc[8][8];
    #pragma unroll
    for (int i = 0; i < 8; i++)
        #pragma unroll
        for (int j = 0; j < 8; j++) acc[i][j] = 0.f;

    for (int k0 = 0; k0 < H_; k0 += BK) {
        #pragma unroll
        for (int i = 0; i < 8; i++) {            // A tile: 128 x 16 (gathered)
            int elem = tid + i * 256;
            int m = elem >> 4;
            int kk = elem & 15;
            int gm = m0 + m;
            float v = 0.f;
            if (gm < cnt) {
                int tok = g_slot_tok[e * C_ + gm];
                v = xf[(size_t)tok * H_ + k0 + kk];
            }
            As[kk][m] = v;
        }
        #pragma unroll
        for (int i = 0; i < 8; i++) {            // B tile: 16 x 128
            int elem = tid + i * 256;
            int kk = elem >> 7;
            int n = elem & 127;
            Bs[kk][n] = B[(size_t)(k0 + kk) * (2 * F_) + n0 + n];
        }
        __syncthreads();

        #pragma unroll
        for (int k = 0; k < BK; k++) {
            float a[8], b[8];
            #pragma unroll
            for (int i = 0; i < 4; i++) {
                a[i]     = As[k][ty * 4 + i];
                a[4 + i] = As[k][64 + ty * 4 + i];
            }
            #pragma unroll
            for (int j = 0; j < 4; j++) {
                b[j]     = Bs[k][tx * 4 + j];
                b[4 + j] = Bs[k][64 + tx * 4 + j];
            }
            #pragma unroll
            for (int i = 0; i < 8; i++)
                #pragma unroll
                for (int j = 0; j < 8; j++)
                    acc[i][j] += a[i] * b[j];
        }
        __syncthreads();
    }

    // epilogue: interleaved GLU; column pairs (even, odd) -> act[f = n/2]
    const float* bias = w1_bias + (size_t)e * (2 * F_);
    #pragma unroll
    for (int i = 0; i < 8; i++) {
        int m = m0 + ((i < 4) ? (ty * 4 + i) : (64 + ty * 4 + (i - 4)));
        if (m >= cnt) continue;
        float* actp = g_act + ((size_t)e * C_ + m) * F_;
        #pragma unroll
        for (int j = 0; j < 8; j += 2) {
            int n = n0 + ((j < 4) ? (tx * 4 + j) : (64 + tx * 4 + (j - 4)));
            float gu0 = acc[i][j]     + bias[n];
            float gu1 = acc[i][j + 1] + bias[n + 1];
            float gate = fminf(gu0, LIMIT_);
            float up   = fminf(fmaxf(gu1, -LIMIT_), LIMIT_);
            float glu  = gate / (1.0f + expf(-ALPHA_ * gate));
            actp[n >> 1] = (up + 1.0f) * glu;
        }
    }
}

// -------------------- GEMM2: act @ w2 + b2 -> weighted atomic scatter ------
__global__ void __launch_bounds__(256, 2)
gemm2_kernel(const float* __restrict__ w2,
             const float* __restrict__ w2_bias,
             float* __restrict__ out) {
    int e = blockIdx.z;
    int cnt = g_cnt[e];
    int m0 = blockIdx.y * BM;
    if (m0 >= cnt) return;
    int n0 = blockIdx.x * BN;

    const float* A = g_act + (size_t)e * C_ * F_;
    const float* B = w2 + (size_t)e * F_ * H_;

    __shared__ float As[BK][BM + 4];
    __shared__ float Bs[BK][BN];

    int tid = threadIdx.x;
    int tx = tid & 15;
    int ty = tid >> 4;

    float acc[8][8];
    #pragma unroll
    for (int i = 0; i < 8; i++)
        #pragma unroll
        for (int j = 0; j < 8; j++) acc[i][j] = 0.f;

    for (int k0 = 0; k0 < F_; k0 += BK) {
        #pragma unroll
        for (int i = 0; i < 8; i++) {            // A tile: 128 x 16
            int elem = tid + i * 256;
            int m = elem >> 4;
            int kk = elem & 15;
            int gm = m0 + m;
            float v = 0.f;
            if (gm < cnt) v = A[(size_t)gm * F_ + k0 + kk];
            As[kk][m] = v;
        }
        #pragma unroll
        for (int i = 0; i < 8; i++) {            // B tile: 16 x 128
            int elem = tid + i * 256;
            int kk = elem >> 7;
            int n = elem & 127;
            Bs[kk][n] = B[(size_t)(k0 + kk) * H_ + n0 + n];
        }
        __syncthreads();

        #pragma unroll
        for (int k = 0; k < BK; k++) {
            float a[8], b[8];
            #pragma unroll
            for (int i = 0; i < 4; i++) {
                a[i]     = As[k][ty * 4 + i];
                a[4 + i] = As[k][64 + ty * 4 + i];
            }
            #pragma unroll
            for (int j = 0; j < 4; j++) {
                b[j]     = Bs[k][tx * 4 + j];
                b[4 + j] = Bs[k][64 + tx * 4 + j];
            }
            #pragma unroll
            for (int i = 0; i < 8; i++)
                #pragma unroll
                for (int j = 0; j < 8; j++)
                    acc[i][j] += a[i] * b[j];
        }
        __syncthreads();
    }

    // epilogue: y = acc + b2; out[tok] += w * y (atomic)
    const float* bias = w2_bias + (size_t)e * H_;
    #pragma unroll
    for (int i = 0; i < 8; i++) {
        int m = m0 + ((i < 4) ? (ty * 4 + i) : (64 + ty * 4 + (i - 4)));
        if (m >= cnt) continue;
        int tok   = g_slot_tok[e * C_ + m];
        float wgt = g_slot_w[e * C_ + m];
        float* orow = out + (size_t)tok * H_;
        #pragma unroll
        for (int j = 0; j < 8; j++) {
            int n = n0 + ((j < 4) ? (tx * 4 + j) : (64 + tx * 4 + (j - 4)));
            float y = acc[i][j] + bias[n];
            atomicAdd(&orow[n], wgt * y);
        }
    }
}

// -------------------- launch -----------------------------------------------
extern "C" void kernel_launch(void* const* d_in, const int* in_sizes, int n_in,
                              void* d_out, int out_size) {
    const float* x   = (const float*)d_in[0];  // [SL,BS,H] == [T,H]
    const float* rw  = (const float*)d_in[1];  // [E,H]
    const float* rb  = (const float*)d_in[2];  // [E]
    const float* w1  = (const float*)d_in[3];  // [E,H,2F]
    const float* w2  = (const float*)d_in[4];  // [E,F,H]
    const float* w1b = (const float*)d_in[5];  // [E,2F]
    const float* w2b = (const float*)d_in[6];  // [E,H]

    float* out = (float*)d_out;
    const size_t OUT_MAIN = (size_t)T_ * H_;
    const size_t OUT_EW   = (size_t)T_ * K_;
    const size_t OUT_RS   = (size_t)E_ * T_;
    bool extras = (size_t)out_size >= OUT_MAIN + OUT_EW + OUT_RS;
    float* ew_out = extras ? out + OUT_MAIN : nullptr;
    float* rs_out = extras ? out + OUT_MAIN + OUT_EW : nullptr;

    zero_kernel<<<4096, 256>>>(out, OUT_MAIN);
    router_kernel<<<T_, 128>>>(x, rw, rb, ew_out, rs_out);
    binning_kernel<<<1, 512>>>();

    dim3 g1(2 * F_ / BN, C_ / BM, E_);   // (32, 8, 16)
    gemm1_kernel<<<g1, 256>>>(x, w1, w1b);

    dim3 g2(H_ / BN, C_ / BM, E_);       // (8, 8, 16)
    gemm2_kernel<<<g2, 256>>>(w2, w2b, out);
}

// round 2
// speedup vs baseline: 1.0007x; 1.0007x over previous
#include <cuda_runtime.h>
#include <cuda_bf16.h>
#include <math.h>

// Problem constants (fixed by the dataset)
#define E_  16
#define K_  4
#define H_  1024
#define F_  2048
#define T_  4096            // SL*BS
#define N_  (T_ * K_)       // 16384 routed copies
#define C_  1024            // capacity per expert = K*T/E
#define ALPHA_ 1.702f
#define LIMIT_ 7.0f

#define BM 128
#define BN 128
#define BK 16

// -------------------- scratch (device globals; no runtime allocs) ----------
__device__ float g_act[(size_t)E_ * C_ * F_];   // 128 MB activation scratch
__device__ int   g_slot_tok[E_ * C_];           // slot -> source token
__device__ float g_slot_w[E_ * C_];             // slot -> combine weight
__device__ int   g_cnt[E_];                     // min(tokens_per_expert, C)
__device__ int   g_te[N_];                      // expert id per copy
__device__ float g_ew[N_];                      // softmax weight per copy

// -------------------- zero output -----------------------------------------
__global__ void zero_kernel(float* __restrict__ p, size_t n) {
    size_t i = (size_t)blockIdx.x * blockDim.x + threadIdx.x;
    size_t stride = (size_t)gridDim.x * blockDim.x;
    for (; i < n; i += stride) p[i] = 0.0f;
}

// -------------------- router: logits, top-4, softmax, scores --------------
__global__ void router_kernel(const float* __restrict__ xf,
                              const float* __restrict__ rw,
                              const float* __restrict__ rb,
                              float* __restrict__ ew_out,   // [T,K] or null
                              float* __restrict__ rs_out) { // [E,T] or null
    int t = blockIdx.x;
    int lane = threadIdx.x & 31;
    int w = threadIdx.x >> 5;          // warp 0..3, handles experts 4w..4w+3
    __shared__ float logits[E_];

    const float* xr = xf + (size_t)t * H_;
    float s0 = 0.f, s1 = 0.f, s2 = 0.f, s3 = 0.f;
    const float* r0 = rw + (size_t)(4 * w + 0) * H_;
    const float* r1 = rw + (size_t)(4 * w + 1) * H_;
    const float* r2 = rw + (size_t)(4 * w + 2) * H_;
    const float* r3 = rw + (size_t)(4 * w + 3) * H_;
    for (int i = lane; i < H_; i += 32) {
        float xv = xr[i];
        s0 += xv * r0[i];
        s1 += xv * r1[i];
        s2 += xv * r2[i];
        s3 += xv * r3[i];
    }
    #pragma unroll
    for (int o = 16; o > 0; o >>= 1) {
        s0 += __shfl_xor_sync(0xffffffff, s0, o);
        s1 += __shfl_xor_sync(0xffffffff, s1, o);
        s2 += __shfl_xor_sync(0xffffffff, s2, o);
        s3 += __shfl_xor_sync(0xffffffff, s3, o);
    }
    if (lane == 0) {
        logits[4 * w + 0] = s0 + rb[4 * w + 0];
        logits[4 * w + 1] = s1 + rb[4 * w + 1];
        logits[4 * w + 2] = s2 + rb[4 * w + 2];
        logits[4 * w + 3] = s3 + rb[4 * w + 3];
    }
    __syncthreads();

    if (threadIdx.x == 0) {
        float lv[E_];
        #pragma unroll
        for (int e = 0; e < E_; e++) lv[e] = logits[e];
        int   idx[K_];
        float val[K_];
        bool  used[E_];
        #pragma unroll
        for (int e = 0; e < E_; e++) used[e] = false;
        // top-k: strictly-greater compare with ascending scan -> lowest index
        // wins ties (matches jax.lax.top_k stable semantics)
        for (int k = 0; k < K_; k++) {
            float best = -INFINITY; int bi = 0;
            for (int e = 0; e < E_; e++)
                if (!used[e] && lv[e] > best) { best = lv[e]; bi = e; }
            used[bi] = true; idx[k] = bi; val[k] = best;
        }
        // softmax over the k selected (val[0] is the max)
        float m = val[0], sum = 0.f, p[K_];
        for (int k = 0; k < K_; k++) { p[k] = expf(val[k] - m); sum += p[k]; }
        float inv = 1.0f / sum;
        float sc[E_];
        #pragma unroll
        for (int e = 0; e < E_; e++) sc[e] = 0.f;
        for (int k = 0; k < K_; k++) {
            float wk = p[k] * inv;
            g_ew[t * K_ + k] = wk;
            g_te[t * K_ + k] = idx[k];
            if (ew_out) ew_out[t * K_ + k] = wk;
            sc[idx[k]] = wk;
        }
        if (rs_out) {
            for (int e = 0; e < E_; e++) rs_out[(size_t)e * T_ + t] = sc[e];
        }
    }
}

// -------------------- binning: stable counting sort by expert --------------
// single CTA of 512 threads, each owns 32 consecutive copies
__global__ void binning_kernel() {
    __shared__ int cnts[512 * E_];
    __shared__ int tot[E_];
    int tid = threadIdx.x;
    int base = tid * 32;

    int loc[E_];
    #pragma unroll
    for (int e = 0; e < E_; e++) loc[e] = 0;
    for (int i = 0; i < 32; i++) loc[g_te[base + i]]++;
    #pragma unroll
    for (int e = 0; e < E_; e++) cnts[tid * E_ + e] = loc[e];
    __syncthreads();

    // per-expert exclusive prefix across the 512 threads (16 scanners)
    if (tid < E_) {
        int run = 0;
        for (int i = 0; i < 512; i++) {
            int c = cnts[i * E_ + tid];
            cnts[i * E_ + tid] = run;
            run += c;
        }
        tot[tid] = run;
        g_cnt[tid] = run < C_ ? run : C_;
    }
    __syncthreads();

    // assign slots (per-expert rank), drop rank >= capacity
    #pragma unroll
    for (int e = 0; e < E_; e++) loc[e] = cnts[tid * E_ + e];
    for (int i = 0; i < 32; i++) {
        int n = base + i;
        int e = g_te[n];
        int rank = loc[e]++;
        if (rank < C_) {
            int slot = e * C_ + rank;
            g_slot_tok[slot] = n >> 2;     // / K_
            g_slot_w[slot]   = g_ew[n];
        }
    }
}

// -------------------- GEMM1: xb @ w1 + b1 -> interleaved GLU -> g_act ------
__global__ void __launch_bounds__(256, 2)
gemm1_kernel(const float* __restrict__ xf,
             const float* __restrict__ w1,
             const float* __restrict__ w1_bias) {
    int e = blockIdx.z;
    int cnt = g_cnt[e];
    int m0 = blockIdx.y * BM;
    if (m0 >= cnt) return;
    int n0 = blockIdx.x * BN;

    const float* B = w1 + (size_t)e * H_ * (2 * F_);

    __shared__ float As[BK][BM + 4];
    __shared__ float Bs[BK][BN];

    int tid = threadIdx.x;
    int tx = tid & 15;
    int ty = tid >> 4;

    float acc[8][8];
    #pragma unroll
    for (int i = 0; i < 8; i++)
        #pragma unroll
        for (int j = 0; j < 8; j++) acc[i][j] = 0.f;

    for (int k0 = 0; k0 < H_; k0 += BK) {
        #pragma unroll
        for (int i = 0; i < 8; i++) {            // A tile: 128 x 16 (gathered)
            int elem = tid + i * 256;
            int m = elem >> 4;
            int kk = elem & 15;
            int gm = m0 + m;
            float v = 0.f;
            if (gm < cnt) {
                int tok = g_slot_tok[e * C_ + gm];
                v = xf[(size_t)tok * H_ + k0 + kk];
            }
            As[kk][m] = v;
        }
        #pragma unroll
        for (int i = 0; i < 8; i++) {            // B tile: 16 x 128
            int elem = tid + i * 256;
            int kk = elem >> 7;
            int n = elem & 127;
            Bs[kk][n] = B[(size_t)(k0 + kk) * (2 * F_) + n0 + n];
        }
        __syncthreads();

        #pragma unroll
        for (int k = 0; k < BK; k++) {
            float a[8], b[8];
            #pragma unroll
            for (int i = 0; i < 4; i++) {
                a[i]     = As[k][ty * 4 + i];
                a[4 + i] = As[k][64 + ty * 4 + i];
            }
            #pragma unroll
            for (int j = 0; j < 4; j++) {
                b[j]     = Bs[k][tx * 4 + j];
                b[4 + j] = Bs[k][64 + tx * 4 + j];
            }
            #pragma unroll
            for (int i = 0; i < 8; i++)
                #pragma unroll
                for (int j = 0; j < 8; j++)
                    acc[i][j] += a[i] * b[j];
        }
        __syncthreads();
    }

    // epilogue: interleaved GLU; column pairs (even, odd) -> act[f = n/2]
    const float* bias = w1_bias + (size_t)e * (2 * F_);
    #pragma unroll
    for (int i = 0; i < 8; i++) {
        int m = m0 + ((i < 4) ? (ty * 4 + i) : (64 + ty * 4 + (i - 4)));
        if (m >= cnt) continue;
        float* actp = g_act + ((size_t)e * C_ + m) * F_;
        #pragma unroll
        for (int j = 0; j < 8; j += 2) {
            int n = n0 + ((j < 4) ? (tx * 4 + j) : (64 + tx * 4 + (j - 4)));
            float gu0 = acc[i][j]     + bias[n];
            float gu1 = acc[i][j + 1] + bias[n + 1];
            float gate = fminf(gu0, LIMIT_);
            float up   = fminf(fmaxf(gu1, -LIMIT_), LIMIT_);
            float glu  = gate / (1.0f + expf(-ALPHA_ * gate));
            actp[n >> 1] = (up + 1.0f) * glu;
        }
    }
}

// -------------------- GEMM2: act @ w2 + b2 -> weighted atomic scatter ------
__global__ void __launch_bounds__(256, 2)
gemm2_kernel(const float* __restrict__ w2,
             const float* __restrict__ w2_bias,
             float* __restrict__ out) {
    int e = blockIdx.z;
    int cnt = g_cnt[e];
    int m0 = blockIdx.y * BM;
    if (m0 >= cnt) return;
    int n0 = blockIdx.x * BN;

    const float* A = g_act + (size_t)e * C_ * F_;
    const float* B = w2 + (size_t)e * F_ * H_;

    __shared__ float As[BK][BM + 4];
    __shared__ float Bs[BK][BN];

    int tid = threadIdx.x;
    int tx = tid & 15;
    int ty = tid >> 4;

    float acc[8][8];
    #pragma unroll
    for (int i = 0; i < 8; i++)
        #pragma unroll
        for (int j = 0; j < 8; j++) acc[i][j] = 0.f;

    for (int k0 = 0; k0 < F_; k0 += BK) {
        #pragma unroll
        for (int i = 0; i < 8; i++) {            // A tile: 128 x 16
            int elem = tid + i * 256;
            int m = elem >> 4;
            int kk = elem & 15;
            int gm = m0 + m;
            float v = 0.f;
            if (gm < cnt) v = A[(size_t)gm * F_ + k0 + kk];
            As[kk][m] = v;
        }
        #pragma unroll
        for (int i = 0; i < 8; i++) {            // B tile: 16 x 128
            int elem = tid + i * 256;
            int kk = elem >> 7;
            int n = elem & 127;
            Bs[kk][n] = B[(size_t)(k0 + kk) * H_ + n0 + n];
        }
        __syncthreads();

        #pragma unroll
        for (int k = 0; k < BK; k++) {
            float a[8], b[8];
            #pragma unroll
            for (int i = 0; i < 4; i++) {
                a[i]     = As[k][ty * 4 + i];
                a[4 + i] = As[k][64 + ty * 4 + i];
            }
            #pragma unroll
            for (int j = 0; j < 4; j++) {
                b[j]     = Bs[k][tx * 4 + j];
                b[4 + j] = Bs[k][64 + tx * 4 + j];
            }
            #pragma unroll
            for (int i = 0; i < 8; i++)
                #pragma unroll
                for (int j = 0; j < 8; j++)
                    acc[i][j] += a[i] * b[j];
        }
        __syncthreads();
    }

    // epilogue: y = acc + b2; out[tok] += w * y (atomic)
    const float* bias = w2_bias + (size_t)e * H_;
    #pragma unroll
    for (int i = 0; i < 8; i++) {
        int m = m0 + ((i < 4) ? (ty * 4 + i) : (64 + ty * 4 + (i - 4)));
        if (m >= cnt) continue;
        int tok   = g_slot_tok[e * C_ + m];
        float wgt = g_slot_w[e * C_ + m];
        float* orow = out + (size_t)tok * H_;
        #pragma unroll
        for (int j = 0; j < 8; j++) {
            int n = n0 + ((j < 4) ? (tx * 4 + j) : (64 + tx * 4 + (j - 4)));
            float y = acc[i][j] + bias[n];
            atomicAdd(&orow[n], wgt * y);
        }
    }
}

// -------------------- launch -----------------------------------------------
extern "C" void kernel_launch(void* const* d_in, const int* in_sizes, int n_in,
                              void* d_out, int out_size) {
    const float* x   = (const float*)d_in[0];  // [SL,BS,H] == [T,H]
    const float* rw  = (const float*)d_in[1];  // [E,H]
    const float* rb  = (const float*)d_in[2];  // [E]
    const float* w1  = (const float*)d_in[3];  // [E,H,2F]
    const float* w2  = (const float*)d_in[4];  // [E,F,H]
    const float* w1b = (const float*)d_in[5];  // [E,2F]
    const float* w2b = (const float*)d_in[6];  // [E,H]

    float* out = (float*)d_out;
    const size_t OUT_MAIN = (size_t)T_ * H_;
    const size_t OUT_EW   = (size_t)T_ * K_;
    const size_t OUT_RS   = (size_t)E_ * T_;
    bool extras = (size_t)out_size >= OUT_MAIN + OUT_EW + OUT_RS;
    float* ew_out = extras ? out + OUT_MAIN : nullptr;
    float* rs_out = extras ? out + OUT_MAIN + OUT_EW : nullptr;

    zero_kernel<<<4096, 256>>>(out, OUT_MAIN);
    router_kernel<<<T_, 128>>>(x, rw, rb, ew_out, rs_out);
    binning_kernel<<<1, 512>>>();

    dim3 g1(2 * F_ / BN, C_ / BM, E_);   // (32, 8, 16)
    gemm1_kernel<<<g1, 256>>>(x, w1, w1b);

    dim3 g2(H_ / BN, C_ / BM, E_);       // (8, 8, 16)
    gemm2_kernel<<<g2, 256>>>(w2, w2b, out);
}